// round 14
// baseline (speedup 1.0000x reference)
#include <cuda_runtime.h>
#include <cuda_bf16.h>
#include <cstdint>

// out[b] = ||xdot[b]||^2 + (xdot[b]^T W x[b])^2
//
// SINGLE launch. bf16 hi/lo split HMMA GEMM (U ~= Ah*Bh + Ah*Bl + Al*Bh, fp32
// accum), fp32->bf16 conversion fused into the GEMM mainloop (LDG fp32 ->
// regs -> truncation split -> STS bf16; W tile stored [k][n] and loaded with
// ldmatrix.trans so no pre-transpose pass). Fused bilinear epilogue writes
// deterministic per-(ntile,kz) partials; the last of the 32 CTAs per b-tile
// (modulo-32 atomic election -> no counter reset needed across graph replays)
// sums the fixed slots in fixed order, adds ||xdot||^2, writes out.

#define NB 1024
#define ND 512
#define BM 128
#define BN 64
#define BKC 32            // k per chunk
#define KS 128            // k per CTA (4 chunks)
#define NCH 4
#define LDU 66            // fp32 elems per Us row

// ---------------- scratch ----------------
__device__ float g_partial[32 * NB];
__device__ unsigned g_ctr[8];

// smem stage layout (bytes):
//  Ah [m][k] 128 rows x 80B = 10240   (32 bf16 + 16B pad)
//  Al same                   10240
//  Bh [k][n] 32 rows x 144B = 4608    (64 bf16 + 16B pad; conflict-free trans)
//  Bl same                    4608
#define ST_AH 0
#define ST_AL 10240
#define ST_BH 20480
#define ST_BL 25088
#define STAGE 29696
#define SMEM_MMA (2 * STAGE)   // 59392; Us (128*66*4=33792) reuses smem start

// ---------------- PTX helpers ----------------
__device__ __forceinline__ uint32_t smem_u32(const void* p) {
    uint32_t a;
    asm("{ .reg .u64 t; cvta.to.shared.u64 t, %1; cvt.u32.u64 %0, t; }"
        : "=r"(a) : "l"(p));
    return a;
}
__device__ __forceinline__ void ldsm_x4(uint32_t& r0, uint32_t& r1,
                                        uint32_t& r2, uint32_t& r3, uint32_t addr) {
    asm volatile("ldmatrix.sync.aligned.m8n8.x4.shared.b16 {%0,%1,%2,%3}, [%4];"
                 : "=r"(r0), "=r"(r1), "=r"(r2), "=r"(r3) : "r"(addr));
}
__device__ __forceinline__ void ldsm_x4t(uint32_t& r0, uint32_t& r1,
                                         uint32_t& r2, uint32_t& r3, uint32_t addr) {
    asm volatile("ldmatrix.sync.aligned.m8n8.x4.trans.shared.b16 {%0,%1,%2,%3}, [%4];"
                 : "=r"(r0), "=r"(r1), "=r"(r2), "=r"(r3) : "r"(addr));
}
__device__ __forceinline__ void mma16816(float* c, const uint32_t* a, const uint32_t* b) {
    asm volatile("mma.sync.aligned.m16n8k16.row.col.f32.bf16.bf16.f32 "
                 "{%0,%1,%2,%3}, {%4,%5,%6,%7}, {%8,%9}, {%0,%1,%2,%3};"
                 : "+f"(c[0]), "+f"(c[1]), "+f"(c[2]), "+f"(c[3])
                 : "r"(a[0]), "r"(a[1]), "r"(a[2]), "r"(a[3]), "r"(b[0]), "r"(b[1]));
}

// truncation hi/lo split of a float4 -> packed bf16x2 pairs
// hi = v with low 16 mantissa bits zeroed (exact subtract), lo = rn_bf16(v-hi)
__device__ __forceinline__ void split4(const float4 v, uint2& hi, uint2& lo) {
    uint32_t bx = __float_as_uint(v.x), by = __float_as_uint(v.y);
    uint32_t bz = __float_as_uint(v.z), bw = __float_as_uint(v.w);
    hi.x = __byte_perm(bx, by, 0x7632);
    hi.y = __byte_perm(bz, bw, 0x7632);
    float lx = v.x - __uint_as_float(bx & 0xFFFF0000u);
    float ly = v.y - __uint_as_float(by & 0xFFFF0000u);
    float lz = v.z - __uint_as_float(bz & 0xFFFF0000u);
    float lw = v.w - __uint_as_float(bw & 0xFFFF0000u);
    __nv_bfloat162 l0 = __floats2bfloat162_rn(lx, ly);
    __nv_bfloat162 l1 = __floats2bfloat162_rn(lz, lw);
    lo.x = *(uint32_t*)&l0;
    lo.y = *(uint32_t*)&l1;
}

__global__ __launch_bounds__(256, 2)
void stm_mma(const float* __restrict__ x, const float* __restrict__ xd,
             const float* __restrict__ W, float* __restrict__ out) {
    extern __shared__ __align__(128) char smem[];
    uint32_t sb = smem_u32(smem);
    const int tid = threadIdx.x, wid = tid >> 5, lane = tid & 31;
    const int wm = wid & 3, wn = wid >> 2;       // warp tile (32m x 32n)
    const int n0 = blockIdx.x * BN;
    const int b0 = blockIdx.y * BM;
    const int kz = blockIdx.z;
    const int kbase = kz * KS;

    // per-thread fixed staging coordinates
    const int arow[4] = { (tid + 0) >> 3, (tid + 256) >> 3,
                          (tid + 512) >> 3, (tid + 768) >> 3 };
    const int ac4 = tid & 7;
    const int wrow[2] = { (tid + 0) >> 4, (tid + 256) >> 4 };
    const int wc4 = tid & 15;

    float c[2][4][4];
#pragma unroll
    for (int i = 0; i < 2; i++)
#pragma unroll
        for (int j = 0; j < 4; j++)
#pragma unroll
            for (int r = 0; r < 4; r++) c[i][j][r] = 0.0f;

    float4 va[4], vw[2];

    // ---- prologue: load + convert chunk 0 into buffer 0 ----
#pragma unroll
    for (int p = 0; p < 4; p++)
        va[p] = *(const float4*)(xd + (size_t)(b0 + arow[p]) * ND + kbase + ac4 * 4);
#pragma unroll
    for (int p = 0; p < 2; p++)
        vw[p] = *(const float4*)(W + (size_t)(kbase + wrow[p]) * ND + n0 + wc4 * 4);
    {
        char* st = smem;
#pragma unroll
        for (int p = 0; p < 4; p++) {
            uint2 hi, lo;
            split4(va[p], hi, lo);
            uint32_t off = arow[p] * 80 + ac4 * 8;
            *(uint2*)(st + ST_AH + off) = hi;
            *(uint2*)(st + ST_AL + off) = lo;
        }
#pragma unroll
        for (int p = 0; p < 2; p++) {
            uint2 hi, lo;
            split4(vw[p], hi, lo);
            uint32_t off = wrow[p] * 144 + wc4 * 8;
            *(uint2*)(st + ST_BH + off) = hi;
            *(uint2*)(st + ST_BL + off) = lo;
        }
    }
    __syncthreads();

    for (int ch = 0; ch < NCH; ch++) {
        // issue next chunk's global loads early (latency hidden by mma phase)
        if (ch < NCH - 1) {
            int kc = kbase + (ch + 1) * BKC;
#pragma unroll
            for (int p = 0; p < 4; p++)
                va[p] = *(const float4*)(xd + (size_t)(b0 + arow[p]) * ND + kc + ac4 * 4);
#pragma unroll
            for (int p = 0; p < 2; p++)
                vw[p] = *(const float4*)(W + (size_t)(kc + wrow[p]) * ND + n0 + wc4 * 4);
        }

        uint32_t st = sb + (ch & 1) * STAGE;
#pragma unroll
        for (int kk = 0; kk < BKC; kk += 16) {
            uint32_t ah[2][4], al[2][4];
#pragma unroll
            for (int mb = 0; mb < 2; mb++) {
                int row = wm * 32 + mb * 16 + (lane & 15);
                uint32_t off = row * 80 + (kk + (lane >> 4) * 8) * 2;
                ldsm_x4(ah[mb][0], ah[mb][1], ah[mb][2], ah[mb][3], st + ST_AH + off);
                ldsm_x4(al[mb][0], al[mb][1], al[mb][2], al[mb][3], st + ST_AL + off);
            }
            uint32_t bh[4][2], bl[4][2];
#pragma unroll
            for (int np = 0; np < 2; np++) {
                int kx = kk + (lane & 7) + ((lane >> 3) & 1) * 8;
                int nx = wn * 32 + np * 16 + ((lane >> 4) << 3);
                uint32_t off = kx * 144 + nx * 2;
                ldsm_x4t(bh[2 * np][0], bh[2 * np][1], bh[2 * np + 1][0], bh[2 * np + 1][1],
                         st + ST_BH + off);
                ldsm_x4t(bl[2 * np][0], bl[2 * np][1], bl[2 * np + 1][0], bl[2 * np + 1][1],
                         st + ST_BL + off);
            }
#pragma unroll
            for (int mb = 0; mb < 2; mb++)
#pragma unroll
                for (int nb = 0; nb < 4; nb++) {
                    mma16816(c[mb][nb], ah[mb], bh[nb]);
                    mma16816(c[mb][nb], ah[mb], bl[nb]);
                    mma16816(c[mb][nb], al[mb], bh[nb]);
                }
        }

        // convert + store next chunk into the other buffer
        if (ch < NCH - 1) {
            char* stc = smem + ((ch + 1) & 1) * STAGE;
#pragma unroll
            for (int p = 0; p < 4; p++) {
                uint2 hi, lo;
                split4(va[p], hi, lo);
                uint32_t off = arow[p] * 80 + ac4 * 8;
                *(uint2*)(stc + ST_AH + off) = hi;
                *(uint2*)(stc + ST_AL + off) = lo;
            }
#pragma unroll
            for (int p = 0; p < 2; p++) {
                uint2 hi, lo;
                split4(vw[p], hi, lo);
                uint32_t off = wrow[p] * 144 + wc4 * 8;
                *(uint2*)(stc + ST_BH + off) = hi;
                *(uint2*)(stc + ST_BL + off) = lo;
            }
        }
        __syncthreads();
    }

    // ---- epilogue: accumulators -> smem, per-row dot with x ----
    float* Us = (float*)smem;                     // 128 x LDU fp32
#pragma unroll
    for (int mb = 0; mb < 2; mb++) {
        int row = wm * 32 + mb * 16 + (lane >> 2);
#pragma unroll
        for (int nb = 0; nb < 4; nb++) {
            int col = wn * 32 + nb * 8 + (lane & 3) * 2;
            *(float2*)(Us + row * LDU + col)       = make_float2(c[mb][nb][0], c[mb][nb][1]);
            *(float2*)(Us + (row + 8) * LDU + col) = make_float2(c[mb][nb][2], c[mb][nb][3]);
        }
    }
    __syncthreads();

    {
        int row = tid >> 1, half = tid & 1;       // 2 threads per row, 32 cols each
        const float4* xr = (const float4*)(x + (size_t)(b0 + row) * ND + n0 + half * 32);
        const float* ur = Us + row * LDU + half * 32;
        float s = 0.0f;
#pragma unroll
        for (int q = 0; q < 8; q++) {
            float4 v = xr[q];
            s = fmaf(ur[4 * q + 0], v.x, s);
            s = fmaf(ur[4 * q + 1], v.y, s);
            s = fmaf(ur[4 * q + 2], v.z, s);
            s = fmaf(ur[4 * q + 3], v.w, s);
        }
        s += __shfl_xor_sync(0xffffffffu, s, 1);
        if (half == 0)
            g_partial[(blockIdx.x * NCH + kz) * NB + b0 + row] = s;
    }

    // ---- fused finalize: modulo-32 election (no counter reset needed) ----
    __threadfence();
    __shared__ unsigned s_done;
    if (tid == 0) s_done = atomicAdd(&g_ctr[blockIdx.y], 1u);
    __syncthreads();
    if ((s_done & 31u) == 31u) {
        __threadfence();
        int row = tid >> 1, half = tid & 1;
        int b = b0 + row;
        // ||xdot_b||^2 : each thread handles 256 floats
        const float4* xr = (const float4*)(xd + (size_t)b * ND + half * 256);
        float n2 = 0.0f;
#pragma unroll 8
        for (int q = 0; q < 64; q++) {
            float4 v = xr[q];
            n2 += v.x * v.x + v.y * v.y + v.z * v.z + v.w * v.w;
        }
        // t: half 0 sums slots 0..15, half 1 sums 16..31 (fixed order)
        float tp = 0.0f;
#pragma unroll
        for (int k = 0; k < 16; k++) tp += g_partial[(half * 16 + k) * NB + b];
        float n2o = __shfl_xor_sync(0xffffffffu, n2, 1);
        float tpo = __shfl_xor_sync(0xffffffffu, tp, 1);
        if (half == 0) {
            float t = tp + tpo;
            out[b] = (n2 + n2o) + t * t;
        }
    }
}

// ---------------- launch ----------------
extern "C" void kernel_launch(void* const* d_in, const int* in_sizes, int n_in,
                              void* d_out, int out_size) {
    const float* x    = (const float*)d_in[0];   // [1024, 512]
    const float* xdot = (const float*)d_in[1];   // [1024, 512]
    const float* W    = (const float*)d_in[2];   // [512, 512]
    float* out = (float*)d_out;                  // [1024]

    cudaFuncSetAttribute(stm_mma, cudaFuncAttributeMaxDynamicSharedMemorySize, SMEM_MMA);

    stm_mma<<<dim3(8, 8, 4), 256, SMEM_MMA>>>(x, xdot, W, out);
}